// round 5
// baseline (speedup 1.0000x reference)
#include <cuda_runtime.h>

#define ESP      1e-12f
#define C_DIM    8192
#define THREADS  256
#define GRID     1184           // 148 SMs x 8 blocks resident: one persistent wave

__device__ double        g_accum;   // sum of row losses
__device__ unsigned int  g_work;    // row ticket
__device__ unsigned int  g_done;    // completed-block ticket

__device__ __forceinline__ float fsqrt_approx(float x) {
    float r;
    asm("sqrt.approx.f32 %0, %1;" : "=f"(r) : "f"(x));
    return r;
}

__global__ void mfl_reset_kernel() {
    g_accum = 0.0;
    g_work  = 0u;
    g_done  = 0u;
}

__global__ void __launch_bounds__(THREADS, 8) mfl_fused_kernel(
    const float* __restrict__ p,
    const float* __restrict__ g,
    float* __restrict__ out,
    int n_rows)
{
    const int tid = threadIdx.x;
    const int wid = tid >> 5;
    const int lid = tid & 31;

    __shared__ int   s_row;
    __shared__ float s_sum[THREADS / 32];
    __shared__ int   s_cnt[THREADS / 32];

    double acc = 0.0;   // thread 0's running sum of this block's row losses

    for (;;) {
        if (tid == 0)
            s_row = (int)atomicAdd(&g_work, 1u);
        __syncthreads();
        const int row = s_row;
        __syncthreads();            // s_row safe to overwrite next iter
        if (row >= n_rows) break;

        const float4* __restrict__ p4 =
            reinterpret_cast<const float4*>(p + (size_t)row * C_DIM);
        const float4* __restrict__ g4 =
            reinterpret_cast<const float4*>(g + (size_t)row * C_DIM);

        float sum = 0.0f;
        int   cnt = 0;

        // 2048 float4 per row / 256 threads = 8 per thread per tensor.
        #pragma unroll
        for (int i = 0; i < 8; i++) {
            float4 pv = __ldcs(&p4[tid + i * THREADS]);
            float4 gv = __ldcs(&g4[tid + i * THREADS]);

            #pragma unroll
            for (int k = 0; k < 4; k++) {
                float pe = (&pv.x)[k];
                float ge = (&gv.x)[k];
                float a = fmaf(pe, ge, ESP);
                float b = fmaf(1.0f - pe, 1.0f - ge, ESP);
                float l = 1.0f - (fsqrt_approx(a) + fsqrt_approx(b));
                bool nz = (ge != 0.0f);
                sum += nz ? l : 0.0f;
                cnt += nz ? 1 : 0;
            }
        }

        #pragma unroll
        for (int o = 16; o > 0; o >>= 1) {
            sum += __shfl_down_sync(0xffffffffu, sum, o);
            cnt += __shfl_down_sync(0xffffffffu, cnt, o);
        }
        if (lid == 0) {
            s_sum[wid] = sum;
            s_cnt[wid] = cnt;
        }
        __syncthreads();

        if (tid == 0) {
            float bsum = 0.0f;
            int   bcnt = 0;
            #pragma unroll
            for (int w = 0; w < THREADS / 32; w++) {
                bsum += s_sum[w];
                bcnt += s_cnt[w];
            }
            acc += (bcnt > 0) ? (double)(bsum / (float)bcnt) : 0.0;
        }
        __syncthreads();            // s_sum/s_cnt safe to overwrite next iter
    }

    // One atomic per block; last finished block finalizes.
    if (tid == 0) {
        atomicAdd(&g_accum, acc);
        __threadfence();
        unsigned int t = atomicAdd(&g_done, 1u);
        if (t == (unsigned int)(gridDim.x - 1)) {
            double total = atomicAdd(&g_accum, 0.0);   // atomic read-after-fence
            out[0] = (float)(total / (double)n_rows);
        }
    }
}

extern "C" void kernel_launch(void* const* d_in, const int* in_sizes, int n_in,
                              void* d_out, int out_size) {
    const float* p = (const float*)d_in[0];
    const float* g = (const float*)d_in[1];
    float* out = (float*)d_out;

    const int total = in_sizes[0];
    const int n_rows = total / C_DIM;   // 16384

    mfl_reset_kernel<<<1, 1>>>();
    mfl_fused_kernel<<<GRID, THREADS>>>(p, g, out, n_rows);
}